// round 9
// baseline (speedup 1.0000x reference)
#include <cuda_runtime.h>
#include <cstdint>

// Problem constants
#define DIMC   512
#define HEADSC 8
#define NTOK   64          // tokens per window (8x8)
#define BWIN   2048        // number of windows (32*64)
#define MROWS  (BWIN*NTOK) // 131072
#define PER_LAT 225

// ---------------- scratch (static device memory; allocation is forbidden) ----
__device__ float g_q [BWIN*HEADSC*NTOK*64];  // [B][H][N][D], tf32-rounded, q pre-scaled
__device__ float g_k [BWIN*HEADSC*NTOK*64];
__device__ float g_v [BWIN*HEADSC*NTOK*64];
__device__ float g_ao[(size_t)MROWS*DIMC];   // attention output (tf32-rounded), [M,512]
__device__ float g_wq[3*DIMC*DIMC];          // w_qkv pre-rounded
__device__ float g_wp[DIMC*DIMC];            // w_proj pre-rounded

// ---------------- tf32 helpers ----------------------------------------------
__device__ __forceinline__ uint32_t f2tf(float x){
    uint32_t r; asm volatile("cvt.rna.tf32.f32 %0, %1;" : "=r"(r) : "f"(x)); return r;
}
__device__ __forceinline__ uint32_t f2tf_b(uint32_t bits){
    uint32_t r; asm volatile("cvt.rna.tf32.f32 %0, %1;" : "=r"(r) : "f"(__uint_as_float(bits)));
    return r;
}
__device__ __forceinline__ void mma8(float* c, const uint32_t* a, const uint32_t* b){
    asm volatile(
      "mma.sync.aligned.m16n8k8.row.col.f32.tf32.tf32.f32 "
      "{%0,%1,%2,%3}, {%4,%5,%6,%7}, {%8,%9}, {%0,%1,%2,%3};"
      : "+f"(c[0]), "+f"(c[1]), "+f"(c[2]), "+f"(c[3])
      : "r"(a[0]), "r"(a[1]), "r"(a[2]), "r"(a[3]), "r"(b[0]), "r"(b[1]));
}
__device__ __forceinline__ void ldm_x4(uint32_t* r, uint32_t addr){
    asm volatile("ldmatrix.sync.aligned.m8n8.x4.shared.b16 {%0,%1,%2,%3}, [%4];"
                 : "=r"(r[0]), "=r"(r[1]), "=r"(r[2]), "=r"(r[3]) : "r"(addr));
}
__device__ __forceinline__ void cp16(uint32_t dst, const void* src){
    asm volatile("cp.async.cg.shared.global [%0], [%1], 16;\n" :: "r"(dst), "l"(src));
}

// ---------------- pre-round pass: dst = tf32_rna(src) ------------------------
__global__ void round_tf32(const float* __restrict__ src, float* __restrict__ dst, int n4){
    int i = blockIdx.x * blockDim.x + threadIdx.x;
    const int stride = gridDim.x * blockDim.x;
    for (; i < n4; i += stride){
        float4 v = ((const float4*)src)[i];
        ((uint4*)dst)[i] = make_uint4(f2tf(v.x), f2tf(v.y), f2tf(v.z), f2tf(v.w));
    }
}

// ---------------- GEMM: C[M,N] = A[M,K] * W[N,K]^T + bias[N] -----------------
// MODE 0: A = raw f32 x (fragments cvt'd to tf32 in-register); epilogue -> q/k/v
// MODE 1: A = tf32-valued g_ao; plain epilogue -> out
// Block 128x128x32, 256 threads (8 warps as 2(M) x 4(N), warp tile 64x32).
// 3-stage cp.async pipeline, single __syncthreads per ktile, ldmatrix fragments.
// 110.6 KB smem + ~115 regs -> 2 CTAs/SM = 16 warps/SM. K fixed at 512.
#define SRW 36                         // smem row stride in words
#define STAGE_WORDS (2*128*SRW)        // A[128][36] + B[128][36] = 9216 words
#define GSTAGES 3
#define GSMEM_BYTES (GSTAGES*STAGE_WORDS*4)   // 110592

template<int MODE>
__global__ void __launch_bounds__(256, 2)
gemm_tf32(const float* __restrict__ A, const float* __restrict__ W,
          const float* __restrict__ bias, float* __restrict__ out)
{
    extern __shared__ uint32_t sm[];
    const uint32_t sbase = (uint32_t)__cvta_generic_to_shared(sm);

    const int tid  = threadIdx.x;
    const int lane = tid & 31;
    const int wid  = tid >> 5;           // 0..7
    const int n0   = blockIdx.x * 128;   // n fast: weight panels stay L2-resident
    const int m0   = blockIdx.y * 128;
    const int g    = lane >> 2;
    const int t4   = lane & 3;
    const int wm   = (wid & 1) * 64;     // M: 2 warps
    const int wn   = (wid >> 1) * 32;    // N: 4 warps

    const float* Ag = A + (size_t)m0 * 512;
    const float* Wg = W + (size_t)n0 * 512;

    // ldmatrix per-lane word offsets within a stage
    const int aoff_w = (wm + (lane & 7) + ((lane >> 3) & 1) * 8) * SRW + ((lane >> 4) & 1) * 4;
    const int boff_w = 128*SRW + (wn + (lane & 7) + ((lane >> 4) & 1) * 8) * SRW + ((lane >> 3) & 1) * 4;

    float acc[4][4][4];
    #pragma unroll
    for (int i=0;i<4;i++)
      #pragma unroll
      for (int j=0;j<4;j++)
        #pragma unroll
        for (int e=0;e<4;e++) acc[i][j][e] = 0.f;

    // staging: 2048 16B-chunks per ktile, 8 per thread (A first 1024, then B)
    auto issue = [&](int kt, int stage){
        const uint32_t so_base = sbase + (uint32_t)stage * (STAGE_WORDS*4);
        #pragma unroll
        for (int p=0;p<8;p++){
            const int c    = p*256 + tid;       // 0..2047
            const int row  = (c >> 3) & 127;
            const int col4 = c & 7;
            const float* gp = ((p < 4) ? Ag : Wg) + (size_t)row*512 + kt*32 + col4*4;
            const uint32_t so = so_base + (uint32_t)(((p < 4 ? 0 : 128*SRW)) + row*SRW + col4*4) * 4;
            cp16(so, gp);
        }
        asm volatile("cp.async.commit_group;\n" ::);
    };

    issue(0, 0);
    issue(1, 1);

    for (int kt = 0; kt < 16; kt++){
        asm volatile("cp.async.wait_group 1;\n" ::);   // stage kt resident (in-order groups)
        __syncthreads();                               // kt visible to all; all done reading (kt-1)%3
        if (kt + 2 < 16) issue(kt + 2, (kt + 2) % 3);  // overwrites stage (kt-1)%3 — safe post-sync
        else             asm volatile("cp.async.commit_group;\n" ::);  // keep FIFO uniform

        const uint32_t sA = sbase + (uint32_t)(kt % 3) * (STAGE_WORDS*4);
        #pragma unroll
        for (int ks=0; ks<4; ks++){
            uint32_t af[4][4];
            #pragma unroll
            for (int i=0;i<4;i++){
                ldm_x4(af[i], sA + (uint32_t)(aoff_w + i*16*SRW + ks*8) * 4);
                if (MODE == 0){   // A is raw f32: round fragments to tf32 (rna)
                    af[i][0] = f2tf_b(af[i][0]);
                    af[i][1] = f2tf_b(af[i][1]);
                    af[i][2] = f2tf_b(af[i][2]);
                    af[i][3] = f2tf_b(af[i][3]);
                }
            }
            #pragma unroll
            for (int j2=0;j2<2;j2++){
                uint32_t bq[4];
                ldm_x4(bq, sA + (uint32_t)(boff_w + j2*16*SRW + ks*8) * 4);
                #pragma unroll
                for (int i=0;i<4;i++){
                    mma8(acc[i][2*j2],   af[i], bq);
                    mma8(acc[i][2*j2+1], af[i], bq+2);
                }
            }
        }
    }

    // epilogue. c-frag: e0:(g,2t) e1:(g,2t+1) e2:(g+8,2t) e3:(g+8,2t+1)
    #pragma unroll
    for (int i=0;i<4;i++){
        const int r0 = m0 + wm + i*16 + g;
        #pragma unroll
        for (int j=0;j<4;j++){
            const int c0 = n0 + wn + j*8 + 2*t4;
            #pragma unroll
            for (int e=0;e<4;e++){
                const int r = r0 + (e >> 1) * 8;
                const int c = c0 + (e & 1);
                float v = acc[i][j][e] + bias[c];
                if (MODE == 0){
                    const int s  = c >> 9;
                    const int hh = (c >> 6) & 7;
                    const int d  = c & 63;
                    const int bq = r >> 6;
                    const int t  = r & 63;
                    const int off = (((bq*8 + hh)*64 + t) << 6) + d;
                    // store tf32-rounded so downstream consumers skip cvt
                    if (s == 0)      g_q[off] = __uint_as_float(f2tf(v * 0.125f));
                    else if (s == 1) g_k[off] = __uint_as_float(f2tf(v));
                    else             g_v[off] = __uint_as_float(f2tf(v));
                } else {
                    out[(size_t)r * 512 + c] = v;   // final output: full f32
                }
            }
        }
    }
}

// ---------------- fused attention per (window b, head h) ---------------------
// 128 threads = 4 warps; warp w owns S/O rows [16w, 16w+16).
// ldmatrix fragment loads; P aliases the Q buffer (per-warp-private rows).
// bias analytic: idx2d(r,c) = ((r>>3)-(c>>3)+7)*15 + ((r&7)-(c&7)+7).
#define ATTN_SMEM_WORDS (3*64*68 + 240)    // 13296 words = 53184 B -> 4 CTAs/SM
__global__ void __launch_bounds__(128)
attn_kernel(const float* __restrict__ btab, float* __restrict__ attno)
{
    extern __shared__ uint32_t smw[];
    uint32_t* sq   = smw;              // [64][68] tf32 bits; P overwrites in place
    uint32_t* sk   = sq  + 64*68;
    uint32_t* svT  = sk  + 64*68;      // V transposed: [d][m]
    float*    sbias = (float*)(svT + 64*68);

    const int bh  = blockIdx.x;
    const int b   = bh >> 3;
    const int h   = bh & 7;
    const int lat = b >> 6;
    const int tid = threadIdx.x;
    const int lane = tid & 31;
    const int w   = tid >> 5;
    const int g   = lane >> 2;
    const int t4  = lane & 3;
    const int R0  = w * 16;

    const float* qg = g_q + (size_t)bh * 4096;
    const float* kg = g_k + (size_t)bh * 4096;
    const float* vg = g_v + (size_t)bh * 4096;

    #pragma unroll
    for (int p=0;p<8;p++){
        const int idx = tid + p*128;         // 0..1023
        const int row = idx >> 4;
        const int c4  = (idx & 15) * 4;
        *(uint4*)&sq[row*68 + c4] = *(const uint4*)(qg + row*64 + c4);
        *(uint4*)&sk[row*68 + c4] = *(const uint4*)(kg + row*64 + c4);
        float4 v4 = *(const float4*)(vg + row*64 + c4);
        svT[(c4+0)*68 + row] = __float_as_uint(v4.x);
        svT[(c4+1)*68 + row] = __float_as_uint(v4.y);
        svT[(c4+2)*68 + row] = __float_as_uint(v4.z);
        svT[(c4+3)*68 + row] = __float_as_uint(v4.w);
    }
    for (int i = tid; i < PER_LAT; i += 128)
        sbias[i] = btab[(lat*PER_LAT + i)*8 + h];
    __syncthreads();

    const uint32_t sbase = (uint32_t)__cvta_generic_to_shared(smw);
    // ldmatrix lane addresses (bytes), before the ks*32B column step
    const uint32_t aAddr = sbase + 4u*(uint32_t)((R0 + (lane & 7) + ((lane >> 3) & 1)*8)*68
                                                 + ((lane >> 4) & 1)*4);
    const uint32_t kAddr = sbase + 4u*(uint32_t)(64*68 + ((lane & 7) + ((lane >> 4) & 1)*8)*68
                                                 + ((lane >> 3) & 1)*4);
    const uint32_t vAddr = kAddr + 4u*(uint32_t)(64*68);
    const uint32_t J2 = 16*68*4;       // byte step between 16-row groups

    // ---- S = (Q*scale) K^T ----
    float sacc[8][4];
    #pragma unroll
    for (int j=0;j<8;j++){ sacc[j][0]=0.f; sacc[j][1]=0.f; sacc[j][2]=0.f; sacc[j][3]=0.f; }
    #pragma unroll
    for (int ks=0; ks<8; ks++){
        uint32_t a[4];
        ldm_x4(a, aAddr + ks*32);
        #pragma unroll
        for (int j2=0;j2<4;j2++){
            uint32_t bq[4];
            ldm_x4(bq, kAddr + j2*J2 + ks*32);
            mma8(sacc[2*j2],   a, bq);
            mma8(sacc[2*j2+1], a, bq+2);
        }
    }

    // ---- bias + row softmax + write P (tf32) into sq (aliased) ----
    #pragma unroll
    for (int rr=0; rr<2; rr++){
        const int r   = R0 + g + rr*8;
        const int rR  = r >> 3, rC = r & 7;
        float tmp[16];
        float mx = -1e30f;
        #pragma unroll
        for (int j=0;j<8;j++){
            #pragma unroll
            for (int e=0;e<2;e++){
                const int c  = j*8 + 2*t4 + e;
                const int ib = (rR - (c>>3) + 7)*15 + (rC - (c&7) + 7);
                const float s = sacc[j][rr*2+e] + sbias[ib];
                tmp[j*2+e] = s;
                mx = fmaxf(mx, s);
            }
        }
        mx = fmaxf(mx, __shfl_xor_sync(0xffffffffu, mx, 1));
        mx = fmaxf(mx, __shfl_xor_sync(0xffffffffu, mx, 2));
        float sum = 0.f;
        #pragma unroll
        for (int i=0;i<16;i++){ tmp[i] = __expf(tmp[i]-mx); sum += tmp[i]; }
        sum += __shfl_xor_sync(0xffffffffu, sum, 1);
        sum += __shfl_xor_sync(0xffffffffu, sum, 2);
        const float rinv = 1.f / sum;
        #pragma unroll
        for (int j=0;j<8;j++)
            #pragma unroll
            for (int e=0;e<2;e++){
                const int c = j*8 + 2*t4 + e;
                sq[r*68 + c] = f2tf(tmp[j*2+e] * rinv);
            }
    }
    __syncwarp();   // warp-private rows: writes visible to own warp's ldmatrix

    // ---- O = P V ----
    float oacc[8][4];
    #pragma unroll
    for (int j=0;j<8;j++){ oacc[j][0]=0.f; oacc[j][1]=0.f; oacc[j][2]=0.f; oacc[j][3]=0.f; }
    #pragma unroll
    for (int ks=0; ks<8; ks++){
        uint32_t a[4];
        ldm_x4(a, aAddr + ks*32);          // P fragments (aliased sq)
        #pragma unroll
        for (int j2=0;j2<4;j2++){
            uint32_t bq[4];
            ldm_x4(bq, vAddr + j2*J2 + ks*32);
            mma8(oacc[2*j2],   a, bq);
            mma8(oacc[2*j2+1], a, bq+2);
        }
    }

    // write O (tf32-rounded; proj GEMM consumes raw) -> attno[(b*64+r)*512 + h*64 + d]
    float* ob = attno + (size_t)b * 64 * 512 + h * 64;
    #pragma unroll
    for (int j=0;j<8;j++){
        const int c0 = j*8 + 2*t4;
        const int r  = R0 + g;
        ob[(size_t)r*512     + c0    ] = __uint_as_float(f2tf(oacc[j][0]));
        ob[(size_t)r*512     + c0 + 1] = __uint_as_float(f2tf(oacc[j][1]));
        ob[(size_t)(r+8)*512 + c0    ] = __uint_as_float(f2tf(oacc[j][2]));
        ob[(size_t)(r+8)*512 + c0 + 1] = __uint_as_float(f2tf(oacc[j][3]));
    }
}

// ---------------- launch -----------------------------------------------------
extern "C" void kernel_launch(void* const* d_in, const int* in_sizes, int n_in,
                              void* d_out, int out_size)
{
    const float* x     = (const float*)d_in[0];
    const float* wqkv  = (const float*)d_in[1];
    const float* bqkv  = (const float*)d_in[2];
    const float* wproj = (const float*)d_in[3];
    const float* bproj = (const float*)d_in[4];
    const float* btab  = (const float*)d_in[5];
    // d_in[6] = rel_idx: unused — computed analytically in-kernel.
    float* out = (float*)d_out;

    float *gwq, *gwp, *gao;
    cudaGetSymbolAddress((void**)&gwq, g_wq);
    cudaGetSymbolAddress((void**)&gwp, g_wp);
    cudaGetSymbolAddress((void**)&gao, g_ao);

    cudaFuncSetAttribute(gemm_tf32<0>, cudaFuncAttributeMaxDynamicSharedMemorySize, GSMEM_BYTES);
    cudaFuncSetAttribute(gemm_tf32<1>, cudaFuncAttributeMaxDynamicSharedMemorySize, GSMEM_BYTES);
    const int attn_smem = ATTN_SMEM_WORDS * 4;   // 53184 B
    cudaFuncSetAttribute(attn_kernel, cudaFuncAttributeMaxDynamicSharedMemorySize, attn_smem);

    // pre-round weights to tf32 (rna) once; x is cvt'd in-register inside gemm<0>
    round_tf32<<<768,  256>>>(wqkv,  gwq, 3*DIMC*DIMC/4);
    round_tf32<<<256,  256>>>(wproj, gwp, DIMC*DIMC/4);

    // QKV GEMM: M=131072, N=1536, K=512 (A = raw x)
    gemm_tf32<0><<<dim3(12, 1024), 256, GSMEM_BYTES>>>(x, gwq, bqkv, nullptr);
    // attention: one block per (window, head)
    attn_kernel<<<BWIN*HEADSC, 128, attn_smem>>>(btab, gao);
    // projection GEMM: M=131072, N=512, K=512 (A = tf32-valued g_ao)
    gemm_tf32<1><<<dim3(4, 1024), 256, GSMEM_BYTES>>>(gao, gwp, bproj, out);
}

// round 10
// speedup vs baseline: 1.9146x; 1.9146x over previous
#include <cuda_runtime.h>
#include <cuda_fp16.h>
#include <cstdint>

// Problem constants
#define DIMC   512
#define HEADSC 8
#define NTOK   64          // tokens per window (8x8)
#define BWIN   2048        // number of windows (32*64)
#define MROWS  (BWIN*NTOK) // 131072
#define PER_LAT 225

// ---------------- scratch (static device memory; allocation is forbidden) ----
__device__ __half g_q [BWIN*HEADSC*NTOK*64]; // [B][H][N][D] fp16, q pre-scaled by 0.125
__device__ __half g_k [BWIN*HEADSC*NTOK*64];
__device__ __half g_v [BWIN*HEADSC*NTOK*64];
__device__ __half g_ao[(size_t)MROWS*DIMC];  // attention output fp16, [M,512]
__device__ __half g_xh[(size_t)MROWS*DIMC];  // x rounded to fp16
__device__ __half g_wq[3*DIMC*DIMC];         // w_qkv fp16
__device__ __half g_wp[DIMC*DIMC];           // w_proj fp16

// ---------------- helpers ----------------------------------------------------
__device__ __forceinline__ void mma16(float* c, const uint32_t* a, const uint32_t* b){
    asm volatile(
      "mma.sync.aligned.m16n8k16.row.col.f32.f16.f16.f32 "
      "{%0,%1,%2,%3}, {%4,%5,%6,%7}, {%8,%9}, {%0,%1,%2,%3};"
      : "+f"(c[0]), "+f"(c[1]), "+f"(c[2]), "+f"(c[3])
      : "r"(a[0]), "r"(a[1]), "r"(a[2]), "r"(a[3]), "r"(b[0]), "r"(b[1]));
}
__device__ __forceinline__ void ldm_x4(uint32_t* r, uint32_t addr){
    asm volatile("ldmatrix.sync.aligned.m8n8.x4.shared.b16 {%0,%1,%2,%3}, [%4];"
                 : "=r"(r[0]), "=r"(r[1]), "=r"(r[2]), "=r"(r[3]) : "r"(addr));
}
__device__ __forceinline__ void ldm_x4t(uint32_t* r, uint32_t addr){
    asm volatile("ldmatrix.sync.aligned.m8n8.x4.trans.shared.b16 {%0,%1,%2,%3}, [%4];"
                 : "=r"(r[0]), "=r"(r[1]), "=r"(r[2]), "=r"(r[3]) : "r"(addr));
}
__device__ __forceinline__ void cp16(uint32_t dst, const void* src){
    asm volatile("cp.async.cg.shared.global [%0], [%1], 16;\n" :: "r"(dst), "l"(src));
}
__device__ __forceinline__ uint32_t h2u(half2 h){ return *reinterpret_cast<uint32_t*>(&h); }

// ---------------- pre-round pass: dst = fp16_rn(src) -------------------------
__global__ void round_half(const float* __restrict__ src, __half* __restrict__ dst, int n4){
    int i = blockIdx.x * blockDim.x + threadIdx.x;
    const int stride = gridDim.x * blockDim.x;
    for (; i < n4; i += stride){
        float4 v = ((const float4*)src)[i];
        half2 h0 = __floats2half2_rn(v.x, v.y);
        half2 h1 = __floats2half2_rn(v.z, v.w);
        ((uint2*)dst)[i] = make_uint2(h2u(h0), h2u(h1));
    }
}

// ---------------- fp16 GEMM: C[M,N] = A[M,K] * W[N,K]^T + bias[N] ------------
// MODE 0: epilogue -> q/k/v fp16 scatter (q scaled); MODE 1: -> f32 out.
// Block 128x128, 128 threads (4 warps, 64x64 tiles), ktile 64, 3-stage cp.async,
// ldmatrix fragments. K fixed at 512 (8 ktiles).
#define SRH 72                          // smem row stride in halfs (36 words -> conflict-free)
#define STAGE_BYTES (256*SRH*2)         // A[128][72]h + B[128][72]h = 36864
#define GSTAGES 3
#define GSMEM_BYTES (GSTAGES*STAGE_BYTES)     // 110592

template<int MODE>
__global__ void __launch_bounds__(128)
gemm_f16(const __half* __restrict__ A, const __half* __restrict__ W,
         const float* __restrict__ bias, float* __restrict__ out)
{
    extern __shared__ uint8_t smem[];
    const uint32_t sbase = (uint32_t)__cvta_generic_to_shared(smem);

    const int tid  = threadIdx.x;
    const int lane = tid & 31;
    const int wid  = tid >> 5;
    const int n0   = blockIdx.x * 128;   // n fast: weight panels stay L2-resident
    const int m0   = blockIdx.y * 128;
    const int g    = lane >> 2;
    const int t4   = lane & 3;
    const int wm   = (wid & 1) * 64;
    const int wn   = (wid >> 1) * 64;

    const __half* Ag = A + (size_t)m0 * 512;
    const __half* Wg = W + (size_t)n0 * 512;

    // ldmatrix per-lane half-offsets within a stage
    const int aoff_h = (wm + (lane & 7) + ((lane >> 3) & 1)*8) * SRH + ((lane >> 4) & 1)*8;
    const int boff_h = 128*SRH + (wn + (lane & 7) + ((lane >> 4) & 1)*8) * SRH + ((lane >> 3) & 1)*8;

    float acc[4][8][4];
    #pragma unroll
    for (int i=0;i<4;i++)
      #pragma unroll
      for (int j=0;j<8;j++)
        #pragma unroll
        for (int e=0;e<4;e++) acc[i][j][e] = 0.f;

    // staging: 2048 16B chunks (8 halfs) per ktile, 16 per thread
    auto issue = [&](int kt, int stage){
        const uint32_t so_base = sbase + (uint32_t)stage * STAGE_BYTES;
        #pragma unroll
        for (int p=0;p<16;p++){
            const int c    = p*128 + tid;       // 0..2047
            const int row  = c >> 3;            // 0..255 (A:0-127, B:128-255)
            const int col8 = (c & 7) * 8;
            const __half* gp = ((p < 8) ? Ag + (size_t)row*512
                                        : Wg + (size_t)(row-128)*512) + kt*64 + col8;
            cp16(so_base + (uint32_t)(row*SRH + col8) * 2, gp);
        }
        asm volatile("cp.async.commit_group;\n" ::);
    };

    issue(0, 0);
    issue(1, 1);

    for (int kt = 0; kt < 8; kt++){
        asm volatile("cp.async.wait_group 1;\n" ::);   // stage kt resident
        __syncthreads();                               // visible; all done reading (kt-1)%3
        if (kt + 2 < 8) issue(kt + 2, (kt + 2) % 3);
        else            asm volatile("cp.async.commit_group;\n" ::);

        const uint32_t sA = sbase + (uint32_t)(kt % 3) * STAGE_BYTES;
        #pragma unroll
        for (int ks=0; ks<4; ks++){                    // k16 chunks
            uint32_t af[4][4];
            #pragma unroll
            for (int i=0;i<4;i++)
                ldm_x4(af[i], sA + (uint32_t)(aoff_h + i*16*SRH + ks*16) * 2);
            #pragma unroll
            for (int j2=0;j2<4;j2++){
                uint32_t bq[4];
                ldm_x4(bq, sA + (uint32_t)(boff_h + j2*16*SRH + ks*16) * 2);
                #pragma unroll
                for (int i=0;i<4;i++){
                    mma16(acc[i][2*j2],   af[i], bq);
                    mma16(acc[i][2*j2+1], af[i], bq+2);
                }
            }
        }
    }

    // epilogue. c-frag: e0:(g,2t) e1:(g,2t+1) e2:(g+8,2t) e3:(g+8,2t+1)
    #pragma unroll
    for (int i=0;i<4;i++){
        const int r0 = m0 + wm + i*16 + g;
        #pragma unroll
        for (int j=0;j<8;j++){
            const int c0 = n0 + wn + j*8 + 2*t4;      // even
            float v0 = acc[i][j][0] + bias[c0];
            float v1 = acc[i][j][1] + bias[c0+1];
            float v2 = acc[i][j][2] + bias[c0];
            float v3 = acc[i][j][3] + bias[c0+1];
            if (MODE == 0){
                const int s  = c0 >> 9;
                const int hh = (c0 >> 6) & 7;
                const int d  = c0 & 63;
                const int bq = r0 >> 6;
                const int t  = r0 & 63;
                const int off  = (((bq*8 + hh)*64 + t) << 6) + d;
                const int off2 = off + (8 << 6);      // row +8, same window
                if (s == 0){
                    *(half2*)&g_q[off]  = __floats2half2_rn(v0*0.125f, v1*0.125f);
                    *(half2*)&g_q[off2] = __floats2half2_rn(v2*0.125f, v3*0.125f);
                } else if (s == 1){
                    *(half2*)&g_k[off]  = __floats2half2_rn(v0, v1);
                    *(half2*)&g_k[off2] = __floats2half2_rn(v2, v3);
                } else {
                    *(half2*)&g_v[off]  = __floats2half2_rn(v0, v1);
                    *(half2*)&g_v[off2] = __floats2half2_rn(v2, v3);
                }
            } else {
                out[(size_t)r0*512 + c0]       = v0;
                out[(size_t)r0*512 + c0 + 1]   = v1;
                out[(size_t)(r0+8)*512 + c0]   = v2;
                out[(size_t)(r0+8)*512 + c0+1] = v3;
            }
        }
    }
}

// ---------------- fused attention per (window b, head h), fp16 ---------------
// 128 threads = 4 warps; warp w owns S/O rows [16w, 16w+16).
// Q/K row-major, V row-major (transposed in-flight via ldmatrix.trans).
// P aliases Q rows (warp-private). bias analytic from 225-entry slab.
#define ATTN_SMEM_BYTES (3*64*SRH*2 + 240*4)   // 28608 B
__global__ void __launch_bounds__(128)
attn_kernel(const float* __restrict__ btab, __half* __restrict__ attno)
{
    extern __shared__ uint8_t smem[];
    __half* sq = (__half*)smem;            // [64][72]; P overwrites in place
    __half* sk = sq + 64*SRH;
    __half* sv = sk + 64*SRH;              // V row-major [token][d]
    float*  sbias = (float*)(sv + 64*SRH);

    const int bh  = blockIdx.x;
    const int b   = bh >> 3;
    const int h   = bh & 7;
    const int lat = b >> 6;
    const int tid = threadIdx.x;
    const int lane = tid & 31;
    const int w   = tid >> 5;
    const int g   = lane >> 2;
    const int t4  = lane & 3;
    const int R0  = w * 16;

    const __half* qg = g_q + (size_t)bh * 4096;
    const __half* kg = g_k + (size_t)bh * 4096;
    const __half* vg = g_v + (size_t)bh * 4096;

    #pragma unroll
    for (int p=0;p<4;p++){
        const int idx = tid + p*128;        // 0..511
        const int row = idx >> 3;
        const int c8  = (idx & 7) * 8;
        *(uint4*)&sq[row*SRH + c8] = *(const uint4*)(qg + row*64 + c8);
        *(uint4*)&sk[row*SRH + c8] = *(const uint4*)(kg + row*64 + c8);
        *(uint4*)&sv[row*SRH + c8] = *(const uint4*)(vg + row*64 + c8);
    }
    for (int i = tid; i < PER_LAT; i += 128)
        sbias[i] = btab[(lat*PER_LAT + i)*8 + h];
    __syncthreads();

    const uint32_t sbase = (uint32_t)__cvta_generic_to_shared(smem);
    const uint32_t aAddr = sbase + 2u*(uint32_t)((R0 + (lane & 7) + ((lane >> 3) & 1)*8)*SRH
                                                 + ((lane >> 4) & 1)*8);
    const uint32_t kAddr = sbase + 2u*(uint32_t)(64*SRH + ((lane & 7) + ((lane >> 4) & 1)*8)*SRH
                                                 + ((lane >> 3) & 1)*8);
    const uint32_t vAddr = sbase + 2u*(uint32_t)(2*64*SRH + ((lane & 7) + ((lane >> 3) & 1)*8)*SRH
                                                 + ((lane >> 4) & 1)*8);
    const uint32_t JROW = 16*SRH*2;         // byte step: 16 rows

    // ---- S = (Q*scale) K^T ----
    float sacc[8][4];
    #pragma unroll
    for (int j=0;j<8;j++){ sacc[j][0]=0.f; sacc[j][1]=0.f; sacc[j][2]=0.f; sacc[j][3]=0.f; }
    #pragma unroll
    for (int ks=0; ks<4; ks++){
        uint32_t a[4];
        ldm_x4(a, aAddr + ks*32);
        #pragma unroll
        for (int j2=0;j2<4;j2++){
            uint32_t bq[4];
            ldm_x4(bq, kAddr + j2*JROW + ks*32);
            mma16(sacc[2*j2],   a, bq);
            mma16(sacc[2*j2+1], a, bq+2);
        }
    }

    // ---- bias + row softmax + write P (fp16) into sq (aliased) ----
    #pragma unroll
    for (int rr=0; rr<2; rr++){
        const int r   = R0 + g + rr*8;
        const int rR  = r >> 3, rC = r & 7;
        float tmp[16];
        float mx = -1e30f;
        #pragma unroll
        for (int j=0;j<8;j++){
            #pragma unroll
            for (int e=0;e<2;e++){
                const int c  = j*8 + 2*t4 + e;
                const int ib = (rR - (c>>3) + 7)*15 + (rC - (c&7) + 7);
                const float s = sacc[j][rr*2+e] + sbias[ib];
                tmp[j*2+e] = s;
                mx = fmaxf(mx, s);
            }
        }
        mx = fmaxf(mx, __shfl_xor_sync(0xffffffffu, mx, 1));
        mx = fmaxf(mx, __shfl_xor_sync(0xffffffffu, mx, 2));
        float sum = 0.f;
        #pragma unroll
        for (int i=0;i<16;i++){ tmp[i] = __expf(tmp[i]-mx); sum += tmp[i]; }
        sum += __shfl_xor_sync(0xffffffffu, sum, 1);
        sum += __shfl_xor_sync(0xffffffffu, sum, 2);
        const float rinv = 1.f / sum;
        #pragma unroll
        for (int j=0;j<8;j++)
            *(half2*)&sq[r*SRH + j*8 + 2*t4] =
                __floats2half2_rn(tmp[2*j]*rinv, tmp[2*j+1]*rinv);
    }
    __syncwarp();   // warp-private rows: P visible to own warp's ldmatrix

    // ---- O = P V (V transposed in-flight) ----
    float oacc[8][4];
    #pragma unroll
    for (int j=0;j<8;j++){ oacc[j][0]=0.f; oacc[j][1]=0.f; oacc[j][2]=0.f; oacc[j][3]=0.f; }
    #pragma unroll
    for (int ks=0; ks<4; ks++){             // k16 chunks over tokens
        uint32_t a[4];
        ldm_x4(a, aAddr + ks*32);           // P fragments (aliased sq)
        #pragma unroll
        for (int j2=0;j2<4;j2++){           // d16 groups
            uint32_t bq[4];
            ldm_x4t(bq, vAddr + ks*JROW + j2*32);
            mma16(oacc[2*j2],   a, bq);
            mma16(oacc[2*j2+1], a, bq+2);
        }
    }

    // write O fp16 -> attno[(b*64+r)*512 + h*64 + d]
    __half* ob = attno + (size_t)b * 64 * 512 + h * 64;
    #pragma unroll
    for (int j=0;j<8;j++){
        const int c0 = j*8 + 2*t4;
        const int r  = R0 + g;
        *(half2*)&ob[(size_t)r*512 + c0]     = __floats2half2_rn(oacc[j][0], oacc[j][1]);
        *(half2*)&ob[(size_t)(r+8)*512 + c0] = __floats2half2_rn(oacc[j][2], oacc[j][3]);
    }
}

// ---------------- launch -----------------------------------------------------
extern "C" void kernel_launch(void* const* d_in, const int* in_sizes, int n_in,
                              void* d_out, int out_size)
{
    const float* x     = (const float*)d_in[0];
    const float* wqkv  = (const float*)d_in[1];
    const float* bqkv  = (const float*)d_in[2];
    const float* wproj = (const float*)d_in[3];
    const float* bproj = (const float*)d_in[4];
    const float* btab  = (const float*)d_in[5];
    // d_in[6] = rel_idx: unused — computed analytically in-kernel.
    float* out = (float*)d_out;

    __half *gxh, *gwq, *gwp, *gao;
    cudaGetSymbolAddress((void**)&gxh, g_xh);
    cudaGetSymbolAddress((void**)&gwq, g_wq);
    cudaGetSymbolAddress((void**)&gwp, g_wp);
    cudaGetSymbolAddress((void**)&gao, g_ao);

    cudaFuncSetAttribute(gemm_f16<0>, cudaFuncAttributeMaxDynamicSharedMemorySize, GSMEM_BYTES);
    cudaFuncSetAttribute(gemm_f16<1>, cudaFuncAttributeMaxDynamicSharedMemorySize, GSMEM_BYTES);
    cudaFuncSetAttribute(attn_kernel, cudaFuncAttributeMaxDynamicSharedMemorySize, ATTN_SMEM_BYTES);

    // round operands to fp16 (rn) once
    round_half<<<8192, 256>>>(x,     gxh, (int)((size_t)MROWS*DIMC/4));
    round_half<<<768,  256>>>(wqkv,  gwq, 3*DIMC*DIMC/4);
    round_half<<<256,  256>>>(wproj, gwp, DIMC*DIMC/4);

    // QKV GEMM: M=131072, N=1536, K=512
    gemm_f16<0><<<dim3(12, 1024), 128, GSMEM_BYTES>>>(gxh, gwq, bqkv, nullptr);
    // attention: one block per (window, head)
    attn_kernel<<<BWIN*HEADSC, 128, ATTN_SMEM_BYTES>>>(btab, gao);
    // projection GEMM: M=131072, N=512, K=512
    gemm_f16<1><<<dim3(4, 1024), 128, GSMEM_BYTES>>>(gao, gwp, bproj, out);
}